// round 2
// baseline (speedup 1.0000x reference)
#include <cuda_runtime.h>
#include <cstdint>

#define N 4096
#define H 64
#define NLAYER 3
#define MAXD 128
#define NEG 0.2f
#define EPS 1e-5f
#define SLICES 32
#define FIN_BLOCKS (N / 8)   // 512

// ---------------- scratch (no allocations allowed) ----------------
__device__ float g_x[N * H];          // embedding output (residual)
__device__ float g_h[N * H];          // current hidden
__device__ float g_hw[N * H];         // h @ W_l
__device__ float g_ssrc[N];
__device__ float g_sdst[N];
__device__ int   g_deg[N];
__device__ int   g_cols[N * MAXD];
__device__ float g_c1[H], g_c2[H], g_c3[H];
__device__ float g_part[FIN_BLOCKS * H];

// ---------------- k_prep: init degree lists (self-loop) + fold embedding MLP ----------------
// x = (feat @ W1 + b1) @ W2 + b2 with feat=[progress, hard] collapses to
// x[i] = progress*c1 + hard*c2 + c3, c* precomputed here.
__global__ void k_prep(const float* __restrict__ w1, const float* __restrict__ b1,
                       const float* __restrict__ w2, const float* __restrict__ b2) {
    int gid = blockIdx.x * blockDim.x + threadIdx.x;
    if (gid < N) {
        g_deg[gid] = 1;                 // self loop occupies slot 0
        g_cols[gid * MAXD] = gid;
    }
    if (gid < H) {
        float c1 = 0.f, c2 = 0.f, c3 = 0.f;
        #pragma unroll 8
        for (int k = 0; k < H; k++) {
            float w = w2[k * H + gid];
            c1 += w1[k] * w;
            c2 += w1[H + k] * w;
            c3 += b1[k] * w;
        }
        g_c1[gid] = c1; g_c2[gid] = c2; g_c3[gid] = c3 + b2[gid];
    }
}

// ---------------- k_embed: per-node features -> x (and h) ----------------
__global__ void k_embed(const int* __restrict__ ts,
                        const float* __restrict__ arr, const float* __restrict__ dep,
                        const float* __restrict__ hard) {
    int idx = blockIdx.x * blockDim.x + threadIdx.x;   // N*H threads
    int i = idx >> 6, c = idx & 63;
    // timestep may arrive as int32 or float32; hedge by magnitude.
    int b = *ts;
    float t = (b > -100000 && b < 100000) ? (float)b : __int_as_float(b);
    float p = (t - arr[i]) / (dep[i] - arr[i]);
    float v = p * g_c1[c] + hard[i] * g_c2[c] + g_c3[c];
    g_x[idx] = v;
    g_h[idx] = v;
}

// ---------------- k_edges: build in-neighbor lists from adjacency ----------------
// mask[i][j] = adj[j][i] != 0 (plus self-loop already inserted).
// thread handles destination column i, slice s of source rows j.
// Warp-coalesced reads of adj rows; streaming (read-once).
__global__ void k_edges(const float* __restrict__ adj) {
    int gid = blockIdx.x * blockDim.x + threadIdx.x;   // N*SLICES threads
    int i = gid & (N - 1);
    int s = gid >> 12;
    const int JS = N / SLICES;
    int j0 = s * JS;
    const float* p = adj + (size_t)j0 * N + i;
    #pragma unroll 4
    for (int jj = 0; jj < JS; jj++) {
        float v = __ldcs(p);
        p += N;
        int j = j0 + jj;
        if (v != 0.0f && j != i) {
            int slot = atomicAdd(&g_deg[i], 1);
            if (slot < MAXD) g_cols[i * MAXD + slot] = j;
        }
    }
}

// ---------------- k_gemm: hw = h @ W (4096x64x64), smem tiled, 4x4 reg block ----------------
__global__ void k_gemm(const float* __restrict__ W) {
    __shared__ float sh[64 * 65];   // padded, conflict-free row reads
    __shared__ float sW[64 * 64];
    int tid = threadIdx.x;
    int rbase = blockIdx.x * 64;
    for (int e = tid; e < 64 * 64; e += 256) {
        int r = e >> 6, c = e & 63;
        sh[r * 65 + c] = g_h[(rbase + r) * 64 + c];
        sW[e] = W[e];
    }
    __syncthreads();
    int cg  = tid & 15;             // col group (4 cols)
    int row = (tid >> 4) * 4;       // 4 rows
    float a00=0,a01=0,a02=0,a03=0, a10=0,a11=0,a12=0,a13=0;
    float a20=0,a21=0,a22=0,a23=0, a30=0,a31=0,a32=0,a33=0;
    const float4* sWv = (const float4*)sW;
    #pragma unroll 8
    for (int k = 0; k < 64; k++) {
        float4 w = sWv[k * 16 + cg];
        float h0 = sh[(row + 0) * 65 + k];
        float h1 = sh[(row + 1) * 65 + k];
        float h2 = sh[(row + 2) * 65 + k];
        float h3 = sh[(row + 3) * 65 + k];
        a00 += h0 * w.x; a01 += h0 * w.y; a02 += h0 * w.z; a03 += h0 * w.w;
        a10 += h1 * w.x; a11 += h1 * w.y; a12 += h1 * w.z; a13 += h1 * w.w;
        a20 += h2 * w.x; a21 += h2 * w.y; a22 += h2 * w.z; a23 += h2 * w.w;
        a30 += h3 * w.x; a31 += h3 * w.y; a32 += h3 * w.z; a33 += h3 * w.w;
    }
    float4* out = (float4*)g_hw;
    int ob = ((rbase + row) * 64 + cg * 4) >> 2;   // float4 index
    out[ob]          = make_float4(a00, a01, a02, a03);
    out[ob + 16]     = make_float4(a10, a11, a12, a13);
    out[ob + 32]     = make_float4(a20, a21, a22, a23);
    out[ob + 48]     = make_float4(a30, a31, a32, a33);
}

// ---------------- k_scores: ssrc[i] = hw[i].asrc, sdst[i] = hw[i].adst ----------------
__global__ void k_scores(const float* __restrict__ asrc, const float* __restrict__ adst) {
    int wid = (blockIdx.x * blockDim.x + threadIdx.x) >> 5;
    int lane = threadIdx.x & 31;
    float v0 = g_hw[wid * 64 + lane];
    float v1 = g_hw[wid * 64 + 32 + lane];
    float s = v0 * asrc[lane] + v1 * asrc[32 + lane];
    float d = v0 * adst[lane] + v1 * adst[32 + lane];
    #pragma unroll
    for (int o = 16; o; o >>= 1) {
        s += __shfl_xor_sync(0xffffffffu, s, o);
        d += __shfl_xor_sync(0xffffffffu, d, o);
    }
    if (lane == 0) { g_ssrc[wid] = s; g_sdst[wid] = d; }
}

// ---------------- k_attn: warp per destination row; sparse softmax-aggregate ----------------
// e[i,j] = lrelu(ssrc[j]+sdst[i]); monotone => rowmax = lrelu(max ssrc + sdst).
__global__ void k_attn(const float* __restrict__ bias, int do_relu) {
    int i = (blockIdx.x * blockDim.x + threadIdx.x) >> 5;
    int lane = threadIdx.x & 31;
    int d = g_deg[i]; if (d > MAXD) d = MAXD;
    int base = i * MAXD;
    float sd = g_sdst[i];

    float mx = -1e30f;
    for (int t = lane; t < d; t += 32)
        mx = fmaxf(mx, g_ssrc[g_cols[base + t]]);
    #pragma unroll
    for (int o = 16; o; o >>= 1) mx = fmaxf(mx, __shfl_xor_sync(0xffffffffu, mx, o));
    float m = mx + sd;
    m = m > 0.f ? m : NEG * m;

    float denom = 0.f, acc0 = 0.f, acc1 = 0.f;
    for (int t = 0; t < d; t++) {
        int j = g_cols[base + t];               // warp-uniform -> broadcast
        float e = g_ssrc[j] + sd;
        e = e > 0.f ? e : NEG * e;
        float w = __expf(e - m);
        denom += w;
        acc0 += w * g_hw[j * 64 + lane];
        acc1 += w * g_hw[j * 64 + 32 + lane];
    }
    float inv = 1.0f / denom;
    float o0 = acc0 * inv + bias[lane];
    float o1 = acc1 * inv + bias[32 + lane];
    if (do_relu) { o0 = fmaxf(o0, 0.f); o1 = fmaxf(o1, 0.f); }
    g_h[i * 64 + lane] = o0;
    g_h[i * 64 + 32 + lane] = o1;
}

// ---------------- k_final1: residual + layernorm + per-block column partials ----------------
__global__ void k_final1() {
    __shared__ float sn[8 * 64];
    int w = threadIdx.x >> 5, lane = threadIdx.x & 31;
    int i = blockIdx.x * 8 + w;
    float v0 = g_x[i * 64 + lane]      + g_h[i * 64 + lane];
    float v1 = g_x[i * 64 + 32 + lane] + g_h[i * 64 + 32 + lane];
    float s = v0 + v1;
    #pragma unroll
    for (int o = 16; o; o >>= 1) s += __shfl_xor_sync(0xffffffffu, s, o);
    float mu = s * (1.0f / 64.0f);
    float d0 = v0 - mu, d1 = v1 - mu;
    float q = d0 * d0 + d1 * d1;
    #pragma unroll
    for (int o = 16; o; o >>= 1) q += __shfl_xor_sync(0xffffffffu, q, o);
    float r = rsqrtf(q * (1.0f / 64.0f) + EPS);
    sn[w * 64 + lane]      = d0 * r;
    sn[w * 64 + 32 + lane] = d1 * r;
    __syncthreads();
    if (threadIdx.x < 64) {
        float p = 0.f;
        #pragma unroll
        for (int ww = 0; ww < 8; ww++) p += sn[ww * 64 + threadIdx.x];
        g_part[blockIdx.x * 64 + threadIdx.x] = p;
    }
}

// ---------------- k_final2: finish mean-pool, value head ----------------
__global__ void k_final2(const float* __restrict__ vw, const float* __restrict__ vb,
                         float* __restrict__ out) {
    __shared__ float sm[256];
    int c = threadIdx.x & 63, g = threadIdx.x >> 6;
    float s = 0.f;
    for (int b = g; b < FIN_BLOCKS; b += 4) s += g_part[b * 64 + c];
    sm[threadIdx.x] = s;
    __syncthreads();
    if (threadIdx.x < 64) {
        float pooled = (sm[c] + sm[64 + c] + sm[128 + c] + sm[192 + c]) * (1.0f / (float)N);
        sm[c] = pooled * vw[c];
    }
    __syncthreads();
    if (threadIdx.x < 32) {
        float t = sm[threadIdx.x] + sm[threadIdx.x + 32];
        #pragma unroll
        for (int o = 16; o; o >>= 1) t += __shfl_xor_sync(0xffffffffu, t, o);
        if (threadIdx.x == 0) {
            float r = t + vb[0];
            out[0] = r > 0.f ? r : 0.f;
        }
    }
}

// ---------------- host ----------------
extern "C" void kernel_launch(void* const* d_in, const int* in_sizes, int n_in,
                              void* d_out, int out_size) {
    const float* adj      = (const float*)d_in[0];
    const int*   ts       = (const int*)  d_in[1];
    const float* arrivals = (const float*)d_in[2];
    const float* depart   = (const float*)d_in[3];
    const float* hard     = (const float*)d_in[4];
    // d_in[5] = active_agents: all-ones, unused by reference math
    const float* emb_w1   = (const float*)d_in[6];
    const float* emb_b1   = (const float*)d_in[7];
    const float* emb_w2   = (const float*)d_in[8];
    const float* emb_b2   = (const float*)d_in[9];
    const float* gat_w    = (const float*)d_in[10];
    const float* gat_asrc = (const float*)d_in[11];
    const float* gat_adst = (const float*)d_in[12];
    const float* gat_b    = (const float*)d_in[13];
    const float* val_w    = (const float*)d_in[14];
    const float* val_b    = (const float*)d_in[15];

    k_prep<<<16, 256>>>(emb_w1, emb_b1, emb_w2, emb_b2);
    k_embed<<<(N * H) / 256, 256>>>(ts, arrivals, depart, hard);
    k_edges<<<(N * SLICES) / 256, 256>>>(adj);

    for (int l = 0; l < NLAYER; l++) {
        k_gemm<<<N / 64, 256>>>(gat_w + l * H * H);
        k_scores<<<N / 8, 256>>>(gat_asrc + l * H, gat_adst + l * H);
        k_attn<<<N / 8, 256>>>(gat_b + l * H, (l < NLAYER - 1) ? 1 : 0);
    }

    k_final1<<<FIN_BLOCKS, 256>>>();
    k_final2<<<1, 256>>>(val_w, val_b, (float*)d_out);
}

// round 3
// speedup vs baseline: 1.0345x; 1.0345x over previous
#include <cuda_runtime.h>
#include <cstdint>

#define N 4096
#define H 64
#define NLAYER 3
#define MAXD 128
#define NEG 0.2f
#define EPS 1e-5f
#define ESLICE 64
#define FIN_BLOCKS (N / 8)   // 512

// ---------------- scratch (no allocations allowed) ----------------
__device__ float g_x[N * H];          // embedding output (residual)
__device__ float g_h[N * H];          // current hidden
__device__ float g_hw[N * H];         // h @ W_l
__device__ float g_ssrc[N];
__device__ float g_sdst[N];
__device__ int   g_deg[N];
__device__ int   g_cols[N * MAXD];
__device__ float g_c1[H], g_c2[H], g_c3[H];
__device__ float g_part[FIN_BLOCKS * H];

// ---------------- k_prep: init degree lists (self-loop) + fold embedding MLP ----------------
__global__ void k_prep(const float* __restrict__ w1, const float* __restrict__ b1,
                       const float* __restrict__ w2, const float* __restrict__ b2) {
    int gid = blockIdx.x * blockDim.x + threadIdx.x;
    if (gid < N) {
        g_deg[gid] = 1;                 // self loop occupies slot 0
        g_cols[gid * MAXD] = gid;
    }
    if (gid < H) {
        float c1 = 0.f, c2 = 0.f, c3 = 0.f;
        #pragma unroll 8
        for (int k = 0; k < H; k++) {
            float w = w2[k * H + gid];
            c1 += w1[k] * w;
            c2 += w1[H + k] * w;
            c3 += b1[k] * w;
        }
        g_c1[gid] = c1; g_c2[gid] = c2; g_c3[gid] = c3 + b2[gid];
    }
}

// ---------------- k_embed: per-node features -> x (and h) ----------------
__global__ void k_embed(const int* __restrict__ ts,
                        const float* __restrict__ arr, const float* __restrict__ dep,
                        const float* __restrict__ hard) {
    int idx = blockIdx.x * blockDim.x + threadIdx.x;   // N*H threads
    int i = idx >> 6, c = idx & 63;
    int b = *ts;
    float t = (b > -100000 && b < 100000) ? (float)b : __int_as_float(b);
    float p = (t - arr[i]) / (dep[i] - arr[i]);
    float v = p * g_c1[c] + hard[i] * g_c2[c] + g_c3[c];
    g_x[idx] = v;
    g_h[idx] = v;
}

// ---------------- k_edges: build in-neighbor lists (float4 streaming) ----------------
// mask[i][j] = adj[j][i] != 0. Thread owns 4 dest columns, one row-slice.
__global__ void k_edges(const float* __restrict__ adj) {
    int gid = blockIdx.x * blockDim.x + threadIdx.x;   // (N/4)*ESLICE = 65536 threads
    int i4 = gid & (N / 4 - 1);
    int s = gid >> 10;
    const int JS = N / ESLICE;                          // 64 rows per thread
    int j0 = s * JS;
    const float4* p = (const float4*)adj + (size_t)j0 * (N / 4) + i4;
    int i = i4 * 4;
    #pragma unroll 4
    for (int jj = 0; jj < JS; jj++) {
        float4 v = __ldcs(p);
        p += N / 4;
        int j = j0 + jj;
        if (v.x != 0.f && j != i) {
            int sl = atomicAdd(&g_deg[i], 1);
            if (sl < MAXD) g_cols[i * MAXD + sl] = j;
        }
        if (v.y != 0.f && j != i + 1) {
            int sl = atomicAdd(&g_deg[i + 1], 1);
            if (sl < MAXD) g_cols[(i + 1) * MAXD + sl] = j;
        }
        if (v.z != 0.f && j != i + 2) {
            int sl = atomicAdd(&g_deg[i + 2], 1);
            if (sl < MAXD) g_cols[(i + 2) * MAXD + sl] = j;
        }
        if (v.w != 0.f && j != i + 3) {
            int sl = atomicAdd(&g_deg[i + 3], 1);
            if (sl < MAXD) g_cols[(i + 3) * MAXD + sl] = j;
        }
    }
}

// ---------------- k_gemm: hw = h @ W, 16 rows/block (grid=256) + fused scores ----------------
__global__ void k_gemm(const float* __restrict__ W,
                       const float* __restrict__ asrc, const float* __restrict__ adst) {
    __shared__ float sW[64 * 64];
    __shared__ float sh[16 * 64];
    int tid = threadIdx.x;
    int rbase = blockIdx.x * 16;

    const float4* Wv = (const float4*)W;
    float4* sWv4 = (float4*)sW;
    #pragma unroll 4
    for (int e = tid; e < 1024; e += 256) sWv4[e] = Wv[e];
    const float4* hv = (const float4*)(g_h + rbase * 64);
    ((float4*)sh)[tid] = hv[tid];
    __syncthreads();

    int r = tid >> 4;            // 0..15 row in tile
    int cg = tid & 15;           // 4-col group
    float a0 = 0.f, a1 = 0.f, a2 = 0.f, a3 = 0.f;
    const float4* sWv = (const float4*)sW;
    #pragma unroll 16
    for (int k = 0; k < 64; k++) {
        float4 w = sWv[k * 16 + cg];
        float h0 = sh[r * 64 + k];
        a0 += h0 * w.x; a1 += h0 * w.y; a2 += h0 * w.z; a3 += h0 * w.w;
    }
    ((float4*)g_hw)[(rbase + r) * 16 + cg] = make_float4(a0, a1, a2, a3);

    // fused score epilogue: reduce over the 16 threads owning one row
    float4 as = ((const float4*)asrc)[cg];
    float4 ad = ((const float4*)adst)[cg];
    float s = a0 * as.x + a1 * as.y + a2 * as.z + a3 * as.w;
    float d = a0 * ad.x + a1 * ad.y + a2 * ad.z + a3 * ad.w;
    #pragma unroll
    for (int o = 8; o; o >>= 1) {
        s += __shfl_xor_sync(0xffffffffu, s, o);
        d += __shfl_xor_sync(0xffffffffu, d, o);
    }
    if (cg == 0) { g_ssrc[rbase + r] = s; g_sdst[rbase + r] = d; }
}

// ---------------- k_attn: warp per destination row; sparse softmax-aggregate ----------------
__global__ void k_attn(const float* __restrict__ bias, int do_relu) {
    int i = (blockIdx.x * blockDim.x + threadIdx.x) >> 5;
    int lane = threadIdx.x & 31;
    int d = g_deg[i]; if (d > MAXD) d = MAXD;
    int base = i * MAXD;
    float sd = g_sdst[i];

    float mx = -1e30f;
    for (int t = lane; t < d; t += 32)
        mx = fmaxf(mx, g_ssrc[g_cols[base + t]]);
    #pragma unroll
    for (int o = 16; o; o >>= 1) mx = fmaxf(mx, __shfl_xor_sync(0xffffffffu, mx, o));
    float m = mx + sd;
    m = m > 0.f ? m : NEG * m;

    float denom = 0.f, acc0 = 0.f, acc1 = 0.f;
    for (int t = 0; t < d; t++) {
        int j = g_cols[base + t];               // warp-uniform -> broadcast
        float e = g_ssrc[j] + sd;
        e = e > 0.f ? e : NEG * e;
        float w = __expf(e - m);
        denom += w;
        acc0 += w * g_hw[j * 64 + lane];
        acc1 += w * g_hw[j * 64 + 32 + lane];
    }
    float inv = 1.0f / denom;
    float o0 = acc0 * inv + bias[lane];
    float o1 = acc1 * inv + bias[32 + lane];
    if (do_relu) { o0 = fmaxf(o0, 0.f); o1 = fmaxf(o1, 0.f); }
    g_h[i * 64 + lane] = o0;
    g_h[i * 64 + 32 + lane] = o1;
}

// ---------------- k_final1: residual + layernorm + per-block column partials ----------------
__global__ void k_final1() {
    __shared__ float sn[8 * 64];
    int w = threadIdx.x >> 5, lane = threadIdx.x & 31;
    int i = blockIdx.x * 8 + w;
    float v0 = g_x[i * 64 + lane]      + g_h[i * 64 + lane];
    float v1 = g_x[i * 64 + 32 + lane] + g_h[i * 64 + 32 + lane];
    float s = v0 + v1;
    #pragma unroll
    for (int o = 16; o; o >>= 1) s += __shfl_xor_sync(0xffffffffu, s, o);
    float mu = s * (1.0f / 64.0f);
    float d0 = v0 - mu, d1 = v1 - mu;
    float q = d0 * d0 + d1 * d1;
    #pragma unroll
    for (int o = 16; o; o >>= 1) q += __shfl_xor_sync(0xffffffffu, q, o);
    float r = rsqrtf(q * (1.0f / 64.0f) + EPS);
    sn[w * 64 + lane]      = d0 * r;
    sn[w * 64 + 32 + lane] = d1 * r;
    __syncthreads();
    if (threadIdx.x < 64) {
        float p = 0.f;
        #pragma unroll
        for (int ww = 0; ww < 8; ww++) p += sn[ww * 64 + threadIdx.x];
        g_part[blockIdx.x * 64 + threadIdx.x] = p;
    }
}

// ---------------- k_final2: finish mean-pool, value head ----------------
__global__ void k_final2(const float* __restrict__ vw, const float* __restrict__ vb,
                         float* __restrict__ out) {
    __shared__ float sm[256];
    int c = threadIdx.x & 63, g = threadIdx.x >> 6;
    float s = 0.f;
    for (int b = g; b < FIN_BLOCKS; b += 4) s += g_part[b * 64 + c];
    sm[threadIdx.x] = s;
    __syncthreads();
    if (threadIdx.x < 64) {
        float pooled = (sm[c] + sm[64 + c] + sm[128 + c] + sm[192 + c]) * (1.0f / (float)N);
        sm[c] = pooled * vw[c];
    }
    __syncthreads();
    if (threadIdx.x < 32) {
        float t = sm[threadIdx.x] + sm[threadIdx.x + 32];
        #pragma unroll
        for (int o = 16; o; o >>= 1) t += __shfl_xor_sync(0xffffffffu, t, o);
        if (threadIdx.x == 0) {
            float r = t + vb[0];
            out[0] = r > 0.f ? r : 0.f;
        }
    }
}

// ---------------- host ----------------
extern "C" void kernel_launch(void* const* d_in, const int* in_sizes, int n_in,
                              void* d_out, int out_size) {
    const float* adj      = (const float*)d_in[0];
    const int*   ts       = (const int*)  d_in[1];
    const float* arrivals = (const float*)d_in[2];
    const float* depart   = (const float*)d_in[3];
    const float* hard     = (const float*)d_in[4];
    const float* emb_w1   = (const float*)d_in[6];
    const float* emb_b1   = (const float*)d_in[7];
    const float* emb_w2   = (const float*)d_in[8];
    const float* emb_b2   = (const float*)d_in[9];
    const float* gat_w    = (const float*)d_in[10];
    const float* gat_asrc = (const float*)d_in[11];
    const float* gat_adst = (const float*)d_in[12];
    const float* gat_b    = (const float*)d_in[13];
    const float* val_w    = (const float*)d_in[14];
    const float* val_b    = (const float*)d_in[15];

    k_prep<<<16, 256>>>(emb_w1, emb_b1, emb_w2, emb_b2);
    k_embed<<<(N * H) / 256, 256>>>(ts, arrivals, depart, hard);
    k_edges<<<(N / 4) * ESLICE / 256, 256>>>(adj);

    for (int l = 0; l < NLAYER; l++) {
        k_gemm<<<N / 16, 256>>>(gat_w + l * H * H, gat_asrc + l * H, gat_adst + l * H);
        k_attn<<<N / 8, 256>>>(gat_b + l * H, (l < NLAYER - 1) ? 1 : 0);
    }

    k_final1<<<FIN_BLOCKS, 256>>>();
    k_final2<<<1, 256>>>(val_w, val_b, (float*)d_out);
}

// round 4
// speedup vs baseline: 1.2697x; 1.2273x over previous
#include <cuda_runtime.h>
#include <cstdint>

#define N 4096
#define H 64
#define NLAYER 3
#define MAXD 128
#define NEG 0.2f
#define EPS 1e-5f
#define FIN_BLOCKS (N / 8)   // 512

// ---------------- scratch ----------------
__device__ float g_x[N * H];
__device__ float g_h[N * H];
__device__ float g_hw[N * H];
__device__ float g_ssrc[N];
__device__ float g_sdst[N];
__device__ int   g_deg[N];
__device__ int   g_cols[N * MAXD];
__device__ float g_part[FIN_BLOCKS * H];

// ---------------- k_embed: fold MLP per-block + node features + degree init ----------------
__global__ void k_embed(const int* __restrict__ ts,
                        const float* __restrict__ arr, const float* __restrict__ dep,
                        const float* __restrict__ hard,
                        const float* __restrict__ w1, const float* __restrict__ b1,
                        const float* __restrict__ w2, const float* __restrict__ b2) {
    __shared__ float sc1[64], sc2[64], sc3[64];
    int tid = threadIdx.x;
    if (tid < 64) {
        float c1 = 0.f, c2 = 0.f, c3 = 0.f;
        #pragma unroll 8
        for (int k = 0; k < 64; k++) {
            float w = w2[k * 64 + tid];
            c1 += w1[k] * w;
            c2 += w1[64 + k] * w;
            c3 += b1[k] * w;
        }
        sc1[tid] = c1; sc2[tid] = c2; sc3[tid] = c3 + b2[tid];
    }
    // degree-list init (self loop): grid 64x256 = 16384 threads >= N
    int gi = blockIdx.x * 256 + tid;
    if (gi < N) { g_deg[gi] = 1; g_cols[gi * MAXD] = gi; }
    __syncthreads();

    int b = *ts;
    float t = (b > -100000 && b < 100000) ? (float)b : __int_as_float(b);
    int base = blockIdx.x * 4096;
    #pragma unroll
    for (int it = 0; it < 16; it++) {
        int idx = base + it * 256 + tid;
        int i = idx >> 6, c = idx & 63;
        float p = (t - arr[i]) / (dep[i] - arr[i]);
        float v = p * sc1[c] + hard[i] * sc2[c] + sc3[c];
        g_x[idx] = v;
        g_h[idx] = v;
    }
}

// ---------------- k_edges: build in-neighbor lists (float4 streaming, 128 slices) ----------------
__global__ void k_edges(const float* __restrict__ adj) {
    int gid = blockIdx.x * blockDim.x + threadIdx.x;   // 131072 threads
    int i4 = gid & (N / 4 - 1);
    int s = gid >> 10;                                  // 0..127
    const int JS = 32;
    int j0 = s * JS;
    const float4* p = (const float4*)adj + (size_t)j0 * (N / 4) + i4;
    int i = i4 * 4;
    #pragma unroll 4
    for (int jj = 0; jj < JS; jj++) {
        float4 v = __ldcs(p);
        p += N / 4;
        int j = j0 + jj;
        if (v.x != 0.f && j != i) {
            int sl = atomicAdd(&g_deg[i], 1);
            if (sl < MAXD) g_cols[i * MAXD + sl] = j;
        }
        if (v.y != 0.f && j != i + 1) {
            int sl = atomicAdd(&g_deg[i + 1], 1);
            if (sl < MAXD) g_cols[(i + 1) * MAXD + sl] = j;
        }
        if (v.z != 0.f && j != i + 2) {
            int sl = atomicAdd(&g_deg[i + 2], 1);
            if (sl < MAXD) g_cols[(i + 2) * MAXD + sl] = j;
        }
        if (v.w != 0.f && j != i + 3) {
            int sl = atomicAdd(&g_deg[i + 3], 1);
            if (sl < MAXD) g_cols[(i + 3) * MAXD + sl] = j;
        }
    }
}

// ---------------- k_gemm: one warp per row, W in smem, h via shfl, fused scores ----------------
__global__ void k_gemm(const float* __restrict__ W,
                       const float* __restrict__ asrc, const float* __restrict__ adst) {
    __shared__ float sW[64 * 64];       // 16KB
    int tid = threadIdx.x;
    const float4* Wv = (const float4*)W;
    float4* sWv = (float4*)sW;
    #pragma unroll 4
    for (int e = tid; e < 1024; e += 256) sWv[e] = Wv[e];
    __syncthreads();

    int w = tid >> 5, lane = tid & 31;
    int row = blockIdx.x * 8 + w;
    float h0 = g_h[row * 64 + lane];
    float h1 = g_h[row * 64 + 32 + lane];

    float a0 = 0.f, a1 = 0.f;
    const int c2 = lane * 2;
    #pragma unroll
    for (int k = 0; k < 32; k++) {
        float hk = __shfl_sync(0xffffffffu, h0, k);
        float2 wv = *(const float2*)&sW[k * 64 + c2];
        a0 += hk * wv.x; a1 += hk * wv.y;
    }
    #pragma unroll
    for (int k = 0; k < 32; k++) {
        float hk = __shfl_sync(0xffffffffu, h1, k);
        float2 wv = *(const float2*)&sW[(k + 32) * 64 + c2];
        a0 += hk * wv.x; a1 += hk * wv.y;
    }
    *(float2*)&g_hw[row * 64 + c2] = make_float2(a0, a1);

    float2 as = ((const float2*)asrc)[lane];
    float2 ad = ((const float2*)adst)[lane];
    float s = a0 * as.x + a1 * as.y;
    float d = a0 * ad.x + a1 * ad.y;
    #pragma unroll
    for (int o = 16; o; o >>= 1) {
        s += __shfl_xor_sync(0xffffffffu, s, o);
        d += __shfl_xor_sync(0xffffffffu, d, o);
    }
    if (lane == 0) { g_ssrc[row] = s; g_sdst[row] = d; }
}

// ---------------- k_attn: 2 warps per destination row; sparse softmax-aggregate ----------------
__global__ void k_attn(const float* __restrict__ bias, int do_relu) {
    __shared__ float sacc[8][64];
    __shared__ float sden[8];
    int tid = threadIdx.x;
    int w = tid >> 5, lane = tid & 31;
    int r = w >> 1;                      // local row 0..3
    int half = w & 1;                    // which neighbor subset
    int i = blockIdx.x * 4 + r;

    int d = g_deg[i]; if (d > MAXD) d = MAXD;
    int base = i * MAXD;
    float sd = g_sdst[i];

    // full row max (computed redundantly by both warps; ssrc is L1-hot)
    float mx = -1e30f;
    for (int t = lane; t < d; t += 32)
        mx = fmaxf(mx, g_ssrc[g_cols[base + t]]);
    #pragma unroll
    for (int o = 16; o; o >>= 1) mx = fmaxf(mx, __shfl_xor_sync(0xffffffffu, mx, o));
    float m = mx + sd;
    m = m > 0.f ? m : NEG * m;

    // this warp handles neighbors t = half, half+2, half+4, ...
    float denom = 0.f, acc0 = 0.f, acc1 = 0.f;
    for (int t = half; t < d; t += 2) {
        int j = g_cols[base + t];        // warp-uniform
        float e = g_ssrc[j] + sd;
        e = e > 0.f ? e : NEG * e;
        float wgt = __expf(e - m);
        denom += wgt;
        acc0 += wgt * g_hw[j * 64 + lane];
        acc1 += wgt * g_hw[j * 64 + 32 + lane];
    }
    sacc[w][lane] = acc0;
    sacc[w][32 + lane] = acc1;
    if (lane == 0) sden[w] = denom;
    __syncthreads();

    if (half == 0) {
        float inv = 1.0f / (sden[w] + sden[w + 1]);
        float o0 = (sacc[w][lane]      + sacc[w + 1][lane])      * inv + bias[lane];
        float o1 = (sacc[w][32 + lane] + sacc[w + 1][32 + lane]) * inv + bias[32 + lane];
        if (do_relu) { o0 = fmaxf(o0, 0.f); o1 = fmaxf(o1, 0.f); }
        g_h[i * 64 + lane] = o0;
        g_h[i * 64 + 32 + lane] = o1;
    }
}

// ---------------- k_final1: residual + layernorm + per-block column partials ----------------
__global__ void k_final1() {
    __shared__ float sn[8 * 64];
    int w = threadIdx.x >> 5, lane = threadIdx.x & 31;
    int i = blockIdx.x * 8 + w;
    float v0 = g_x[i * 64 + lane]      + g_h[i * 64 + lane];
    float v1 = g_x[i * 64 + 32 + lane] + g_h[i * 64 + 32 + lane];
    float s = v0 + v1;
    #pragma unroll
    for (int o = 16; o; o >>= 1) s += __shfl_xor_sync(0xffffffffu, s, o);
    float mu = s * (1.0f / 64.0f);
    float d0 = v0 - mu, d1 = v1 - mu;
    float q = d0 * d0 + d1 * d1;
    #pragma unroll
    for (int o = 16; o; o >>= 1) q += __shfl_xor_sync(0xffffffffu, q, o);
    float r = rsqrtf(q * (1.0f / 64.0f) + EPS);
    sn[w * 64 + lane]      = d0 * r;
    sn[w * 64 + 32 + lane] = d1 * r;
    __syncthreads();
    if (threadIdx.x < 64) {
        float p = 0.f;
        #pragma unroll
        for (int ww = 0; ww < 8; ww++) p += sn[ww * 64 + threadIdx.x];
        g_part[blockIdx.x * 64 + threadIdx.x] = p;
    }
}

// ---------------- k_final2: finish mean-pool, value head ----------------
__global__ void k_final2(const float* __restrict__ vw, const float* __restrict__ vb,
                         float* __restrict__ out) {
    __shared__ float sm[256];
    int c = threadIdx.x & 63, g = threadIdx.x >> 6;
    float s = 0.f;
    for (int b = g; b < FIN_BLOCKS; b += 4) s += g_part[b * 64 + c];
    sm[threadIdx.x] = s;
    __syncthreads();
    if (threadIdx.x < 64) {
        float pooled = (sm[c] + sm[64 + c] + sm[128 + c] + sm[192 + c]) * (1.0f / (float)N);
        sm[c] = pooled * vw[c];
    }
    __syncthreads();
    if (threadIdx.x < 32) {
        float t = sm[threadIdx.x] + sm[threadIdx.x + 32];
        #pragma unroll
        for (int o = 16; o; o >>= 1) t += __shfl_xor_sync(0xffffffffu, t, o);
        if (threadIdx.x == 0) {
            float r = t + vb[0];
            out[0] = r > 0.f ? r : 0.f;
        }
    }
}

// ---------------- host ----------------
extern "C" void kernel_launch(void* const* d_in, const int* in_sizes, int n_in,
                              void* d_out, int out_size) {
    const float* adj      = (const float*)d_in[0];
    const int*   ts       = (const int*)  d_in[1];
    const float* arrivals = (const float*)d_in[2];
    const float* depart   = (const float*)d_in[3];
    const float* hard     = (const float*)d_in[4];
    const float* emb_w1   = (const float*)d_in[6];
    const float* emb_b1   = (const float*)d_in[7];
    const float* emb_w2   = (const float*)d_in[8];
    const float* emb_b2   = (const float*)d_in[9];
    const float* gat_w    = (const float*)d_in[10];
    const float* gat_asrc = (const float*)d_in[11];
    const float* gat_adst = (const float*)d_in[12];
    const float* gat_b    = (const float*)d_in[13];
    const float* val_w    = (const float*)d_in[14];
    const float* val_b    = (const float*)d_in[15];

    k_embed<<<64, 256>>>(ts, arrivals, depart, hard, emb_w1, emb_b1, emb_w2, emb_b2);
    k_edges<<<512, 256>>>(adj);

    for (int l = 0; l < NLAYER; l++) {
        k_gemm<<<N / 8, 256>>>(gat_w + l * H * H, gat_asrc + l * H, gat_adst + l * H);
        k_attn<<<N / 4, 256>>>(gat_b + l * H, (l < NLAYER - 1) ? 1 : 0);
    }

    k_final1<<<FIN_BLOCKS, 256>>>();
    k_final2<<<1, 256>>>(val_w, val_b, (float*)d_out);
}